// round 12
// baseline (speedup 1.0000x reference)
#include <cuda_runtime.h>
#include <cstdint>
#include <float.h>

#define N_   2
#define K_   2048
#define DIN_ 1024
#define H_   16
#define D_   64
#define HD_  1024
#define QSCALE 0.18033688011112043f   // 0.125 * log2(e)

// ---------------- device scratch: separated hi/lo planes ----------------
__device__ __align__(16) uint32_t g_ah[3][4096][512];   // input hi (proj A)
__device__ __align__(16) uint32_t g_al[3][4096][512];   // input lo
__device__ __align__(16) uint32_t g_wbh[4][512][1024];  // weights hi (B)
__device__ __align__(16) uint32_t g_wbl[4][512][1024];  // weights lo
__device__ __align__(16) uint32_t g_qph[32][2048][32];  // q hi (scaled), d-pair packed
__device__ __align__(16) uint32_t g_qpl[32][2048][32];
__device__ __align__(16) uint32_t g_kph[32][2048][32];  // k hi
__device__ __align__(16) uint32_t g_kpl[32][2048][32];
__device__ __align__(16) uint32_t g_vh[32][64][1024];   // v hi [nh][d][jpair]
__device__ __align__(16) uint32_t g_vl[32][64][1024];
__device__ __align__(16) float    g_v [32][2048][64];   // v fp32 (for repack)
__device__ __align__(16) uint32_t g_yah[4096][512];     // attn out hi (outproj A)
__device__ __align__(16) uint32_t g_yal[4096][512];
__device__ uint32_t g_mb[(size_t)N_ * K_ * 64];         // packed mask bits

// ---------------- helpers ----------------
__device__ __forceinline__ void bsplit(float x0, float x1, uint32_t& h, uint32_t& l) {
    const uint32_t u0 = __float_as_uint(x0), u1 = __float_as_uint(x1);
    h = __byte_perm(u0, u1, 0x7632);
    const float r0 = x0 - __uint_as_float(u0 & 0xffff0000u);
    const float r1 = x1 - __uint_as_float(u1 & 0xffff0000u);
    asm("cvt.rn.bf16x2.f32 %0, %1, %2;" : "=r"(l) : "f"(r1), "f"(r0));
}
__device__ __forceinline__ void mma_bf16(float* c, const uint32_t* a, const uint32_t* b) {
    asm volatile(
        "mma.sync.aligned.m16n8k16.row.col.f32.bf16.bf16.f32 "
        "{%0,%1,%2,%3}, {%4,%5,%6,%7}, {%8,%9}, {%0,%1,%2,%3};"
        : "+f"(c[0]), "+f"(c[1]), "+f"(c[2]), "+f"(c[3])
        : "r"(a[0]), "r"(a[1]), "r"(a[2]), "r"(a[3]), "r"(b[0]), "r"(b[1]));
}
__device__ __forceinline__ void ldm4(uint32_t* r, uint32_t addr) {
    asm volatile("ldmatrix.sync.aligned.m8n8.x4.shared.b16 {%0,%1,%2,%3}, [%4];"
                 : "=r"(r[0]), "=r"(r[1]), "=r"(r[2]), "=r"(r[3]) : "r"(addr));
}
__device__ __forceinline__ uint32_t smem_u32(const void* p) {
    uint32_t a;
    asm("{ .reg .u64 t; cvta.to.shared.u64 t, %1; cvt.u32.u64 %0, t; }" : "=r"(a) : "l"(p));
    return a;
}
__device__ __forceinline__ float ex2f(float x) {
    float r; asm("ex2.approx.f32 %0, %1;" : "=f"(r) : "f"(x)); return r;
}
__device__ __forceinline__ void cpa(uint32_t dst, const void* src) {
    asm volatile("cp.async.cg.shared.global [%0], [%1], 16;" :: "r"(dst), "l"(src));
}
#define CP_COMMIT() asm volatile("cp.async.commit_group;" ::: "memory")
#define CP_WAIT0()  asm volatile("cp.async.wait_group 0;" ::: "memory")

// ---------------- prep kernels ----------------
__global__ __launch_bounds__(256) void mask_pack(const int* __restrict__ mask) {
    const int idx = blockIdx.x * 256 + threadIdx.x;
    const uint32_t b = __ballot_sync(0xffffffffu, mask[idx] != 0);
    if ((threadIdx.x & 31) == 0) g_mb[idx >> 5] = b;
}

__global__ __launch_bounds__(256) void split_a(const float* __restrict__ q,
    const float* __restrict__ k, const float* __restrict__ v) {
    const int z = blockIdx.y, row = blockIdx.x, c = threadIdx.x;
    const float* src = (z == 0) ? q : (z == 1) ? k : v;
    float4 x = *(const float4*)(src + (size_t)row * DIN_ + c * 4);
    uint32_t h0, l0, h1, l1;
    bsplit(x.x, x.y, h0, l0);
    bsplit(x.z, x.w, h1, l1);
    *(uint2*)&g_ah[z][row][c * 2] = make_uint2(h0, h1);
    *(uint2*)&g_al[z][row][c * 2] = make_uint2(l0, l1);
}

__global__ __launch_bounds__(256) void split_w(const float* __restrict__ wq,
    const float* __restrict__ wk, const float* __restrict__ wv, const float* __restrict__ wp) {
    const int z = blockIdx.y, kp = blockIdx.x, ng = threadIdx.x * 4;
    float4 r0, r1;
    if (z < 3) {
        const float* s = (z == 0) ? wq : (z == 1) ? wk : wv;
        const size_t a0 = (size_t)(ng >> 6) * (DIN_ * D_) + (size_t)(2 * kp) * D_ + (ng & 63);
        r0 = *(const float4*)(s + a0);
        r1 = *(const float4*)(s + a0 + D_);
    } else {
        const size_t a0 = (size_t)(2 * kp) * DIN_ + ng;
        r0 = *(const float4*)(wp + a0);
        r1 = *(const float4*)(wp + a0 + DIN_);
    }
    uint32_t h[4], l[4];
    bsplit(r0.x, r1.x, h[0], l[0]);
    bsplit(r0.y, r1.y, h[1], l[1]);
    bsplit(r0.z, r1.z, h[2], l[2]);
    bsplit(r0.w, r1.w, h[3], l[3]);
    *(uint4*)&g_wbh[z][kp][ng] = make_uint4(h[0], h[1], h[2], h[3]);
    *(uint4*)&g_wbl[z][kp][ng] = make_uint4(l[0], l[1], l[2], l[3]);
}

__global__ __launch_bounds__(256) void repack_v() {
    __shared__ float t[64][68];
    const int nh = blockIdx.y, jt = blockIdx.x, tid = threadIdx.x;
#pragma unroll
    for (int i = 0; i < 4; i++) {
        const int flat = tid + i * 256, tok = flat & 63, d4 = (flat >> 6) * 4;
        *(float4*)&t[tok][d4] = *(const float4*)&g_v[nh][jt * 64 + tok][d4];
    }
    __syncthreads();
    const int jp = tid & 31, dg = tid >> 5;
#pragma unroll
    for (int i = 0; i < 8; i++) {
        const int d = dg * 8 + i;
        uint32_t hh, ll;
        bsplit(t[2 * jp][d], t[2 * jp + 1][d], hh, ll);
        g_vh[nh][d][jt * 32 + jp] = hh;
        g_vl[nh][d][jt * 32 + jp] = ll;
    }
}

// ---------------- GEMM: k32 chunks, cp.async 2-buf pipeline ----------------
// per-buf words: Ah[128][20]=2560 (16 kp data + pad), Al 2560,
//                Bh[16][136]=2176, Bl 2176   -> BUFW 9472 (37.9KB), 2 bufs 75.8KB
#define AHW 0
#define ALW 2560
#define BHW 5120
#define BLW 7296
#define BUFW 9472
#define GEMM_SMEM (2 * BUFW * 4)

__global__ __launch_bounds__(256) void gemm_mma(int mode, const float* __restrict__ bq,
    const float* __restrict__ bk, const float* __restrict__ bv,
    const float* __restrict__ bp, float* __restrict__ outp)
{
    extern __shared__ uint32_t gsm[];
    const uint32_t sb = smem_u32(gsm);

    const int tid = threadIdx.x, wid = tid >> 5, lane = tid & 31;
    const int gid = lane >> 2, tig = lane & 3, wm = wid >> 2, wn = wid & 3;
    const int m0 = blockIdx.x * 128, by = blockIdx.y;
    const int z = (mode == 0) ? blockIdx.z : 3;

    const uint32_t* Ah = (mode == 0) ? &g_ah[z][0][0] : &g_yah[0][0];
    const uint32_t* Al = (mode == 0) ? &g_al[z][0][0] : &g_yal[0][0];
    const uint32_t* Bh = &g_wbh[z][0][0];
    const uint32_t* Bl = &g_wbl[z][0][0];
    const float* bias = (z == 0) ? bq : (z == 1) ? bk : (z == 2) ? bv : bp;

    // cp.async mappings (per k32 chunk: A 128 rows x 16 kp, B 16 kp x 128 n; 2 passes each)
    const int ar = tid >> 1, ac = (tid & 1) * 4;      // A: row, kp group {0..7}; pass2 +8
    const int bkk = tid >> 4, bn = (tid & 15) * 4;    // B: kp row, n group; pass2 +64
    const int bcol = by * 128 + bn;
    const uint32_t daA = sb + (ar * 20 + ac) * 4;
    const uint32_t daB = sb + (BHW + bkk * 136 + bn) * 4;

#define GCP(c, buf) do { \
    const uint32_t bo = (uint32_t)(buf) * BUFW * 4; \
    cpa(daA + bo,                     Ah + (size_t)(m0 + ar) * 512 + (c) * 16 + ac); \
    cpa(daA + bo + 32,                Ah + (size_t)(m0 + ar) * 512 + (c) * 16 + ac + 8); \
    cpa(daA + bo + ALW * 4,           Al + (size_t)(m0 + ar) * 512 + (c) * 16 + ac); \
    cpa(daA + bo + ALW * 4 + 32,      Al + (size_t)(m0 + ar) * 512 + (c) * 16 + ac + 8); \
    cpa(daB + bo,                     Bh + (size_t)((c) * 16 + bkk) * 1024 + bcol); \
    cpa(daB + bo + 256,               Bh + (size_t)((c) * 16 + bkk) * 1024 + bcol + 64); \
    cpa(daB + bo + (BLW - BHW) * 4,        Bl + (size_t)((c) * 16 + bkk) * 1024 + bcol); \
    cpa(daB + bo + (BLW - BHW) * 4 + 256,  Bl + (size_t)((c) * 16 + bkk) * 1024 + bcol + 64); \
    CP_COMMIT(); } while (0)

    GCP(0, 0);

    float acc[4][4][4] = {};

#pragma unroll 2
    for (int c = 0; c < 32; c++) {
        const int buf = c & 1;
        CP_WAIT0();
        __syncthreads();
        if (c + 1 < 32) { GCP(c + 1, buf ^ 1); } else { CP_COMMIT(); }

        const uint32_t bufo = (uint32_t)buf * BUFW;
#pragma unroll
        for (int s = 0; s < 2; s++) {       // two k16 steps within the k32 chunk
            uint32_t ah[4][4], al[4][4];
#pragma unroll
            for (int mt = 0; mt < 4; mt++) {
                const uint32_t off = (wm * 64 + mt * 16 + (lane & 15)) * 20 + s * 8 + (lane >> 4) * 4;
                ldm4(ah[mt], sb + (bufo + AHW + off) * 4);
                ldm4(al[mt], sb + (bufo + ALW + off) * 4);
            }
            uint32_t bh[4][2], bl[4][2];
#pragma unroll
            for (int nt = 0; nt < 4; nt++) {
                const int nc = wn * 32 + nt * 8 + gid;
                bh[nt][0] = gsm[bufo + BHW + (s * 8 + tig) * 136 + nc];
                bh[nt][1] = gsm[bufo + BHW + (s * 8 + tig + 4) * 136 + nc];
                bl[nt][0] = gsm[bufo + BLW + (s * 8 + tig) * 136 + nc];
                bl[nt][1] = gsm[bufo + BLW + (s * 8 + tig + 4) * 136 + nc];
            }
#pragma unroll
            for (int mt = 0; mt < 4; mt++)
#pragma unroll
                for (int nt = 0; nt < 4; nt++) {
                    mma_bf16(acc[mt][nt], ah[mt], bh[nt]);
                    mma_bf16(acc[mt][nt], al[mt], bh[nt]);
                    mma_bf16(acc[mt][nt], ah[mt], bl[nt]);
                }
        }
    }

    // epilogue
#pragma unroll
    for (int mt = 0; mt < 4; mt++)
#pragma unroll
        for (int nt = 0; nt < 4; nt++) {
            const int ng = by * 128 + wn * 32 + nt * 8 + 2 * tig;
            const float b0 = bias[ng], b1 = bias[ng + 1];
#pragma unroll
            for (int half = 0; half < 2; half++) {
                const int m = m0 + wm * 64 + mt * 16 + gid + half * 8;
                float v0 = acc[mt][nt][half * 2 + 0] + b0;
                float v1 = acc[mt][nt][half * 2 + 1] + b1;
                if (mode == 1) {
                    *(float2*)(outp + (size_t)m * HD_ + ng) = make_float2(v0, v1);
                } else {
                    const int nn = m >> 11, kk = m & 2047, h = ng >> 6;
                    if (z == 2) {
                        *(float2*)&g_v[nn * 16 + h][kk][ng & 63] = make_float2(v0, v1);
                    } else {
                        if (z == 0) { v0 *= QSCALE; v1 *= QSCALE; }
                        uint32_t hh, ll;
                        bsplit(v0, v1, hh, ll);
                        const int dp = (ng >> 1) & 31;
                        if (z == 0) { g_qph[nn * 16 + h][kk][dp] = hh; g_qpl[nn * 16 + h][kk][dp] = ll; }
                        else        { g_kph[nn * 16 + h][kk][dp] = hh; g_kpl[nn * 16 + h][kk][dp] = ll; }
                    }
                }
            }
        }
}

// ---------------- flash attention: cp.async 2-buf pipeline ----------------
// per-buf words: Kh[64][36]=2304, Kl 2304, Vh[64][36]=2304, Vl 2304 -> 9216
#define FBUF 9216
#define FLASH_SMEM (2 * FBUF * 4)

__global__ __launch_bounds__(256) void flash_mma()
{
    extern __shared__ uint32_t sm[];
    const uint32_t sb = smem_u32(sm);

    const int qt = blockIdx.x, nh = blockIdx.y, n = nh >> 4, h = nh & 15;
    const int tid = threadIdx.x, w = tid >> 5, lane = tid & 31;
    const int gid = lane >> 2, tig = lane & 3, r0 = w * 16 + gid;

    // ---- stage Q planes (cp.async into buf0: Qh@0, Ql@4608) ----
    {
        const int qr = tid >> 1, qc = (tid & 1) * 16;
        const uint32_t dq = sb + (qr * 36 + qc) * 4;
#pragma unroll
        for (int i = 0; i < 4; i++) {
            cpa(dq + i * 16,            &g_qph[nh][qt * 128 + qr][qc + i * 4]);
            cpa(dq + 4608 * 4 + i * 16, &g_qpl[nh][qt * 128 + qr][qc + i * 4]);
        }
        CP_COMMIT();
    }
    CP_WAIT0();
    __syncthreads();

    uint32_t afh[4][4], afl[4][4];
    {
        const uint32_t off = (uint32_t)(w * 16 + (lane & 15)) * 36 + (lane >> 4) * 4;
#pragma unroll
        for (int sp = 0; sp < 4; sp++) {
            ldm4(afh[sp], sb + (off + sp * 8) * 4);
            ldm4(afl[sp], sb + (4608 + off + sp * 8) * 4);
        }
    }
    __syncthreads();   // all warps done reading Q staging before tile0 overwrite

    // cp.async tile loader mapping
    const int fj = tid >> 2, fq = (tid & 3) * 8;
    const uint32_t dK = sb + (fj * 36 + fq) * 4;
    const uint32_t dV = sb + (4608 + fj * 36 + fq) * 4;

#define FCP(kt, buf) do { \
    cpa(dK + (buf) * FBUF * 4,               &g_kph[nh][(kt) * 64 + fj][fq]); \
    cpa(dK + (buf) * FBUF * 4 + 16,          &g_kph[nh][(kt) * 64 + fj][fq + 4]); \
    cpa(dK + ((buf) * FBUF + 2304) * 4,      &g_kpl[nh][(kt) * 64 + fj][fq]); \
    cpa(dK + ((buf) * FBUF + 2304) * 4 + 16, &g_kpl[nh][(kt) * 64 + fj][fq + 4]); \
    cpa(dV + (buf) * FBUF * 4,               &g_vh[nh][fj][(kt) * 32 + fq]); \
    cpa(dV + (buf) * FBUF * 4 + 16,          &g_vh[nh][fj][(kt) * 32 + fq + 4]); \
    cpa(dV + ((buf) * FBUF + 2304) * 4,      &g_vl[nh][fj][(kt) * 32 + fq]); \
    cpa(dV + ((buf) * FBUF + 2304) * 4 + 16, &g_vl[nh][fj][(kt) * 32 + fq + 4]); \
    CP_COMMIT(); } while (0)

    FCP(0, 0);

    float o[8][4] = {};
    float ls0 = 0.f, ls1 = 0.f;
    const uint32_t* mr0 = g_mb + (size_t)(n * K_ + qt * 128 + r0) * 64;
    const uint32_t* mr1 = mr0 + 8 * 64;

    const uint32_t brow = (lane & 7) + ((lane & 16) ? 8u : 0u);
    const uint32_t bbyt = (lane & 8) ? 16u : 0u;

#pragma unroll 2
    for (int kt = 0; kt < 32; kt++) {
        const int buf = kt & 1;
        // mask prefetch first: LDG latency hides under QK MMAs
        const uint2 w0 = *(const uint2*)(mr0 + kt * 2);
        const uint2 w1 = *(const uint2*)(mr1 + kt * 2);
        CP_WAIT0();
        __syncthreads();
        if (kt + 1 < 32) { FCP(kt + 1, buf ^ 1); } else { CP_COMMIT(); }

        // S = Q K^T (3-term)
        float s[8][4] = {};
#pragma unroll
        for (int sp = 0; sp < 4; sp++) {
#pragma unroll
            for (int g = 0; g < 4; g++) {
                const uint32_t base = (buf * FBUF + (g * 16 + brow) * 36 + sp * 8) * 4 + bbyt;
                uint32_t kh4[4], kl4[4];
                ldm4(kh4, sb + base);
                ldm4(kl4, sb + 2304 * 4 + base);
#pragma unroll
                for (int t = 0; t < 2; t++) {
                    mma_bf16(s[g * 2 + t], afh[sp], kh4 + 2 * t);
                    mma_bf16(s[g * 2 + t], afl[sp], kh4 + 2 * t);
                    mma_bf16(s[g * 2 + t], afh[sp], kl4 + 2 * t);
                }
            }
        }

        // mask + exp2 (no-max softmax)
#pragma unroll
        for (int nt = 0; nt < 8; nt++) {
            const int jb = nt * 8 + 2 * tig;
#pragma unroll
            for (int cc = 0; cc < 4; cc++) {
                const int j = jb + (cc & 1);
                const uint32_t word = (cc < 2) ? ((j < 32) ? w0.x : w0.y)
                                               : ((j < 32) ? w1.x : w1.y);
                s[nt][cc] = ((word >> (j & 31)) & 1u) ? 0.f : ex2f(s[nt][cc]);
            }
            ls0 += s[nt][0] + s[nt][1];
            ls1 += s[nt][2] + s[nt][3];
        }

        // O += P V (P frags in registers)
#pragma unroll
        for (int sp = 0; sp < 4; sp++) {
            uint32_t aph[4], apl[4];
            bsplit(s[2 * sp][0],     s[2 * sp][1],     aph[0], apl[0]);
            bsplit(s[2 * sp][2],     s[2 * sp][3],     aph[1], apl[1]);
            bsplit(s[2 * sp + 1][0], s[2 * sp + 1][1], aph[2], apl[2]);
            bsplit(s[2 * sp + 1][2], s[2 * sp + 1][3], aph[3], apl[3]);
#pragma unroll
            for (int g = 0; g < 4; g++) {
                const uint32_t base = (buf * FBUF + 4608 + (g * 16 + brow) * 36 + sp * 8) * 4 + bbyt;
                uint32_t vh4[4], vl4[4];
                ldm4(vh4, sb + base);
                ldm4(vl4, sb + 2304 * 4 + base);
#pragma unroll
                for (int t = 0; t < 2; t++) {
                    mma_bf16(o[g * 2 + t], aph, vh4 + 2 * t);
                    mma_bf16(o[g * 2 + t], apl, vh4 + 2 * t);
                    mma_bf16(o[g * 2 + t], aph, vl4 + 2 * t);
                }
            }
        }
    }

    // epilogue: row sums, normalize, write split outproj-A planes
    ls0 += __shfl_xor_sync(0xffffffffu, ls0, 1);
    ls0 += __shfl_xor_sync(0xffffffffu, ls0, 2);
    ls1 += __shfl_xor_sync(0xffffffffu, ls1, 1);
    ls1 += __shfl_xor_sync(0xffffffffu, ls1, 2);
    const float i0 = 1.0f / ls0, i1 = 1.0f / ls1;
    const int row = n * K_ + qt * 128 + r0;
#pragma unroll
    for (int dn = 0; dn < 8; dn++) {
        const int dp = h * 32 + dn * 4 + tig;
        uint32_t hh, ll;
        bsplit(o[dn][0] * i0, o[dn][1] * i0, hh, ll);
        g_yah[row][dp] = hh;  g_yal[row][dp] = ll;
        bsplit(o[dn][2] * i1, o[dn][3] * i1, hh, ll);
        g_yah[row + 8][dp] = hh;  g_yal[row + 8][dp] = ll;
    }
}

// ---------------- launch ----------------
extern "C" void kernel_launch(void* const* d_in, const int* in_sizes, int n_in,
                              void* d_out, int out_size)
{
    const float* query = (const float*)d_in[0];
    const float* key   = (const float*)d_in[1];
    const float* value = (const float*)d_in[2];
    const int*   mask  = (const int*)d_in[3];
    const float* Wq = (const float*)d_in[4];
    const float* bq = (const float*)d_in[5];
    const float* Wk = (const float*)d_in[6];
    const float* bk = (const float*)d_in[7];
    const float* Wv = (const float*)d_in[8];
    const float* bv = (const float*)d_in[9];
    const float* Wp = (const float*)d_in[10];
    const float* bp = (const float*)d_in[11];
    float* out = (float*)d_out;

    cudaFuncSetAttribute(gemm_mma, cudaFuncAttributeMaxDynamicSharedMemorySize, GEMM_SMEM);
    cudaFuncSetAttribute(flash_mma, cudaFuncAttributeMaxDynamicSharedMemorySize, FLASH_SMEM);

    mask_pack<<<(N_ * K_ * K_) / 256, 256>>>(mask);
    split_a<<<dim3(4096, 3), 256>>>(query, key, value);
    split_w<<<dim3(512, 4), 256>>>(Wq, Wk, Wv, Wp);
    gemm_mma<<<dim3(32, 8, 3), 256, GEMM_SMEM>>>(0, bq, bk, bv, bp, nullptr);
    repack_v<<<dim3(32, 32), 256>>>();
    flash_mma<<<dim3(16, 32), 256, FLASH_SMEM>>>();
    gemm_mma<<<dim3(32, 8, 1), 256, GEMM_SMEM>>>(1, bq, bk, bv, bp, out);
}

// round 13
// speedup vs baseline: 1.0912x; 1.0912x over previous
#include <cuda_runtime.h>
#include <cstdint>
#include <float.h>

#define N_   2
#define K_   2048
#define DIN_ 1024
#define H_   16
#define D_   64
#define HD_  1024
#define QSCALE 0.18033688011112043f   // 0.125 * log2(e)

// ---------------- device scratch: separated hi/lo planes ----------------
__device__ __align__(16) uint32_t g_ah[3][4096][512];   // input hi (proj A)
__device__ __align__(16) uint32_t g_al[3][4096][512];   // input lo
__device__ __align__(16) uint32_t g_wbh[4][512][1024];  // weights hi (B)
__device__ __align__(16) uint32_t g_wbl[4][512][1024];  // weights lo
__device__ __align__(16) uint32_t g_qph[32][2048][32];  // q hi (scaled), d-pair packed
__device__ __align__(16) uint32_t g_qpl[32][2048][32];
__device__ __align__(16) uint32_t g_kph[32][2048][32];  // k hi
__device__ __align__(16) uint32_t g_kpl[32][2048][32];
__device__ __align__(16) uint32_t g_vh[32][64][1024];   // v hi [nh][d][jpair]
__device__ __align__(16) uint32_t g_vl[32][64][1024];
__device__ __align__(16) float    g_v [32][2048][64];   // v fp32 (for repack)
__device__ __align__(16) uint32_t g_yah[4096][512];     // attn out hi (outproj A)
__device__ __align__(16) uint32_t g_yal[4096][512];
__device__ uint32_t g_mb[(size_t)N_ * K_ * 64];         // packed mask bits

// ---------------- helpers ----------------
__device__ __forceinline__ void bsplit(float x0, float x1, uint32_t& h, uint32_t& l) {
    const uint32_t u0 = __float_as_uint(x0), u1 = __float_as_uint(x1);
    h = __byte_perm(u0, u1, 0x7632);
    const float r0 = x0 - __uint_as_float(u0 & 0xffff0000u);
    const float r1 = x1 - __uint_as_float(u1 & 0xffff0000u);
    asm("cvt.rn.bf16x2.f32 %0, %1, %2;" : "=r"(l) : "f"(r1), "f"(r0));
}
__device__ __forceinline__ void mma_bf16(float* c, const uint32_t* a, const uint32_t* b) {
    asm volatile(
        "mma.sync.aligned.m16n8k16.row.col.f32.bf16.bf16.f32 "
        "{%0,%1,%2,%3}, {%4,%5,%6,%7}, {%8,%9}, {%0,%1,%2,%3};"
        : "+f"(c[0]), "+f"(c[1]), "+f"(c[2]), "+f"(c[3])
        : "r"(a[0]), "r"(a[1]), "r"(a[2]), "r"(a[3]), "r"(b[0]), "r"(b[1]));
}
__device__ __forceinline__ void ldm4(uint32_t* r, uint32_t addr) {
    asm volatile("ldmatrix.sync.aligned.m8n8.x4.shared.b16 {%0,%1,%2,%3}, [%4];"
                 : "=r"(r[0]), "=r"(r[1]), "=r"(r[2]), "=r"(r[3]) : "r"(addr));
}
__device__ __forceinline__ uint32_t smem_u32(const void* p) {
    uint32_t a;
    asm("{ .reg .u64 t; cvta.to.shared.u64 t, %1; cvt.u32.u64 %0, t; }" : "=r"(a) : "l"(p));
    return a;
}
__device__ __forceinline__ float ex2f(float x) {
    float r; asm("ex2.approx.f32 %0, %1;" : "=f"(r) : "f"(x)); return r;
}
__device__ __forceinline__ void cpa(uint32_t dst, const void* src) {
    asm volatile("cp.async.cg.shared.global [%0], [%1], 16;" :: "r"(dst), "l"(src));
}
#define CP_COMMIT() asm volatile("cp.async.commit_group;" ::: "memory")
#define CP_WAIT0()  asm volatile("cp.async.wait_group 0;" ::: "memory")

// ---------------- prep kernels ----------------
__global__ __launch_bounds__(256) void mask_pack(const int* __restrict__ mask) {
    const int idx = blockIdx.x * 256 + threadIdx.x;
    const uint32_t b = __ballot_sync(0xffffffffu, mask[idx] != 0);
    if ((threadIdx.x & 31) == 0) g_mb[idx >> 5] = b;
}

__global__ __launch_bounds__(256) void split_a(const float* __restrict__ q,
    const float* __restrict__ k, const float* __restrict__ v) {
    const int z = blockIdx.y, row = blockIdx.x, c = threadIdx.x;
    const float* src = (z == 0) ? q : (z == 1) ? k : v;
    float4 x = *(const float4*)(src + (size_t)row * DIN_ + c * 4);
    uint32_t h0, l0, h1, l1;
    bsplit(x.x, x.y, h0, l0);
    bsplit(x.z, x.w, h1, l1);
    *(uint2*)&g_ah[z][row][c * 2] = make_uint2(h0, h1);
    *(uint2*)&g_al[z][row][c * 2] = make_uint2(l0, l1);
}

__global__ __launch_bounds__(256) void split_w(const float* __restrict__ wq,
    const float* __restrict__ wk, const float* __restrict__ wv, const float* __restrict__ wp) {
    const int z = blockIdx.y, kp = blockIdx.x, ng = threadIdx.x * 4;
    float4 r0, r1;
    if (z < 3) {
        const float* s = (z == 0) ? wq : (z == 1) ? wk : wv;
        const size_t a0 = (size_t)(ng >> 6) * (DIN_ * D_) + (size_t)(2 * kp) * D_ + (ng & 63);
        r0 = *(const float4*)(s + a0);
        r1 = *(const float4*)(s + a0 + D_);
    } else {
        const size_t a0 = (size_t)(2 * kp) * DIN_ + ng;
        r0 = *(const float4*)(wp + a0);
        r1 = *(const float4*)(wp + a0 + DIN_);
    }
    uint32_t h[4], l[4];
    bsplit(r0.x, r1.x, h[0], l[0]);
    bsplit(r0.y, r1.y, h[1], l[1]);
    bsplit(r0.z, r1.z, h[2], l[2]);
    bsplit(r0.w, r1.w, h[3], l[3]);
    *(uint4*)&g_wbh[z][kp][ng] = make_uint4(h[0], h[1], h[2], h[3]);
    *(uint4*)&g_wbl[z][kp][ng] = make_uint4(l[0], l[1], l[2], l[3]);
}

__global__ __launch_bounds__(256) void repack_v() {
    __shared__ float t[64][68];
    const int nh = blockIdx.y, jt = blockIdx.x, tid = threadIdx.x;
#pragma unroll
    for (int i = 0; i < 4; i++) {
        const int flat = tid + i * 256, tok = flat & 63, d4 = (flat >> 6) * 4;
        *(float4*)&t[tok][d4] = *(const float4*)&g_v[nh][jt * 64 + tok][d4];
    }
    __syncthreads();
    const int jp = tid & 31, dg = tid >> 5;
#pragma unroll
    for (int i = 0; i < 8; i++) {
        const int d = dg * 8 + i;
        uint32_t hh, ll;
        bsplit(t[2 * jp][d], t[2 * jp + 1][d], hh, ll);
        g_vh[nh][d][jt * 32 + jp] = hh;
        g_vl[nh][d][jt * 32 + jp] = ll;
    }
}

// ---------------- GEMM: k32 chunks, cp.async 2-buf pipeline, 2 CTAs/SM ----------------
// per-buf words: Ah[128][20]=2560 (16 kp data + pad), Al 2560,
//                Bh[16][136]=2176, Bl 2176   -> BUFW 9472 (37.9KB), 2 bufs 75.8KB
#define AHW 0
#define ALW 2560
#define BHW 5120
#define BLW 7296
#define BUFW 9472
#define GEMM_SMEM (2 * BUFW * 4)

__global__ __launch_bounds__(256, 2) void gemm_mma(int mode, const float* __restrict__ bq,
    const float* __restrict__ bk, const float* __restrict__ bv,
    const float* __restrict__ bp, float* __restrict__ outp)
{
    extern __shared__ uint32_t gsm[];
    const uint32_t sb = smem_u32(gsm);

    const int tid = threadIdx.x, wid = tid >> 5, lane = tid & 31;
    const int gid = lane >> 2, tig = lane & 3, wm = wid >> 2, wn = wid & 3;
    const int m0 = blockIdx.x * 128, by = blockIdx.y;
    const int z = (mode == 0) ? blockIdx.z : 3;

    const uint32_t* Ah = (mode == 0) ? &g_ah[z][0][0] : &g_yah[0][0];
    const uint32_t* Al = (mode == 0) ? &g_al[z][0][0] : &g_yal[0][0];
    const uint32_t* Bh = &g_wbh[z][0][0];
    const uint32_t* Bl = &g_wbl[z][0][0];
    const float* bias = (z == 0) ? bq : (z == 1) ? bk : (z == 2) ? bv : bp;

    // cp.async mappings (per k32 chunk: A 128 rows x 16 kp, B 16 kp x 128 n; 2 passes each)
    const int ar = tid >> 1, ac = (tid & 1) * 4;      // A: row, kp group {0..7}; pass2 +8
    const int bkk = tid >> 4, bn = (tid & 15) * 4;    // B: kp row, n group; pass2 +64
    const int bcol = by * 128 + bn;
    const uint32_t daA = sb + (ar * 20 + ac) * 4;
    const uint32_t daB = sb + (BHW + bkk * 136 + bn) * 4;

#define GCP(c, buf) do { \
    const uint32_t bo = (uint32_t)(buf) * BUFW * 4; \
    cpa(daA + bo,                     Ah + (size_t)(m0 + ar) * 512 + (c) * 16 + ac); \
    cpa(daA + bo + 32,                Ah + (size_t)(m0 + ar) * 512 + (c) * 16 + ac + 8); \
    cpa(daA + bo + ALW * 4,           Al + (size_t)(m0 + ar) * 512 + (c) * 16 + ac); \
    cpa(daA + bo + ALW * 4 + 32,      Al + (size_t)(m0 + ar) * 512 + (c) * 16 + ac + 8); \
    cpa(daB + bo,                     Bh + (size_t)((c) * 16 + bkk) * 1024 + bcol); \
    cpa(daB + bo + 256,               Bh + (size_t)((c) * 16 + bkk) * 1024 + bcol + 64); \
    cpa(daB + bo + (BLW - BHW) * 4,        Bl + (size_t)((c) * 16 + bkk) * 1024 + bcol); \
    cpa(daB + bo + (BLW - BHW) * 4 + 256,  Bl + (size_t)((c) * 16 + bkk) * 1024 + bcol + 64); \
    CP_COMMIT(); } while (0)

    GCP(0, 0);

    float acc[4][4][4] = {};

#pragma unroll 2
    for (int c = 0; c < 32; c++) {
        const int buf = c & 1;
        CP_WAIT0();
        __syncthreads();
        if (c + 1 < 32) { GCP(c + 1, buf ^ 1); } else { CP_COMMIT(); }

        const uint32_t bufo = (uint32_t)buf * BUFW;
#pragma unroll
        for (int s = 0; s < 2; s++) {       // two k16 steps within the k32 chunk
            uint32_t ah[4][4], al[4][4];
#pragma unroll
            for (int mt = 0; mt < 4; mt++) {
                const uint32_t off = (wm * 64 + mt * 16 + (lane & 15)) * 20 + s * 8 + (lane >> 4) * 4;
                ldm4(ah[mt], sb + (bufo + AHW + off) * 4);
                ldm4(al[mt], sb + (bufo + ALW + off) * 4);
            }
            uint32_t bh[4][2], bl[4][2];
#pragma unroll
            for (int nt = 0; nt < 4; nt++) {
                const int nc = wn * 32 + nt * 8 + gid;
                bh[nt][0] = gsm[bufo + BHW + (s * 8 + tig) * 136 + nc];
                bh[nt][1] = gsm[bufo + BHW + (s * 8 + tig + 4) * 136 + nc];
                bl[nt][0] = gsm[bufo + BLW + (s * 8 + tig) * 136 + nc];
                bl[nt][1] = gsm[bufo + BLW + (s * 8 + tig + 4) * 136 + nc];
            }
#pragma unroll
            for (int mt = 0; mt < 4; mt++)
#pragma unroll
                for (int nt = 0; nt < 4; nt++) {
                    mma_bf16(acc[mt][nt], ah[mt], bh[nt]);
                    mma_bf16(acc[mt][nt], al[mt], bh[nt]);
                    mma_bf16(acc[mt][nt], ah[mt], bl[nt]);
                }
        }
    }

    // epilogue
#pragma unroll
    for (int mt = 0; mt < 4; mt++)
#pragma unroll
        for (int nt = 0; nt < 4; nt++) {
            const int ng = by * 128 + wn * 32 + nt * 8 + 2 * tig;
            const float b0 = bias[ng], b1 = bias[ng + 1];
#pragma unroll
            for (int half = 0; half < 2; half++) {
                const int m = m0 + wm * 64 + mt * 16 + gid + half * 8;
                float v0 = acc[mt][nt][half * 2 + 0] + b0;
                float v1 = acc[mt][nt][half * 2 + 1] + b1;
                if (mode == 1) {
                    *(float2*)(outp + (size_t)m * HD_ + ng) = make_float2(v0, v1);
                } else {
                    const int nn = m >> 11, kk = m & 2047, h = ng >> 6;
                    if (z == 2) {
                        *(float2*)&g_v[nn * 16 + h][kk][ng & 63] = make_float2(v0, v1);
                    } else {
                        if (z == 0) { v0 *= QSCALE; v1 *= QSCALE; }
                        uint32_t hh, ll;
                        bsplit(v0, v1, hh, ll);
                        const int dp = (ng >> 1) & 31;
                        if (z == 0) { g_qph[nn * 16 + h][kk][dp] = hh; g_qpl[nn * 16 + h][kk][dp] = ll; }
                        else        { g_kph[nn * 16 + h][kk][dp] = hh; g_kpl[nn * 16 + h][kk][dp] = ll; }
                    }
                }
            }
        }
}

// ---------------- flash attention: cp.async 2-buf pipeline, 2 CTAs/SM ----------------
// per-buf words: Kh[64][36]=2304, Kl 2304, Vh[64][36]=2304, Vl 2304 -> 9216
#define FBUF 9216
#define FLASH_SMEM (2 * FBUF * 4)

__global__ __launch_bounds__(256, 2) void flash_mma()
{
    extern __shared__ uint32_t sm[];
    const uint32_t sb = smem_u32(sm);

    const int qt = blockIdx.x, nh = blockIdx.y, n = nh >> 4, h = nh & 15;
    const int tid = threadIdx.x, w = tid >> 5, lane = tid & 31;
    const int gid = lane >> 2, tig = lane & 3, r0 = w * 16 + gid;

    // ---- stage Q planes (cp.async into buf0: Qh@0, Ql@4608) ----
    {
        const int qr = tid >> 1, qc = (tid & 1) * 16;
        const uint32_t dq = sb + (qr * 36 + qc) * 4;
#pragma unroll
        for (int i = 0; i < 4; i++) {
            cpa(dq + i * 16,            &g_qph[nh][qt * 128 + qr][qc + i * 4]);
            cpa(dq + 4608 * 4 + i * 16, &g_qpl[nh][qt * 128 + qr][qc + i * 4]);
        }
        CP_COMMIT();
    }
    CP_WAIT0();
    __syncthreads();

    uint32_t afh[4][4], afl[4][4];
    {
        const uint32_t off = (uint32_t)(w * 16 + (lane & 15)) * 36 + (lane >> 4) * 4;
#pragma unroll
        for (int sp = 0; sp < 4; sp++) {
            ldm4(afh[sp], sb + (off + sp * 8) * 4);
            ldm4(afl[sp], sb + (4608 + off + sp * 8) * 4);
        }
    }
    __syncthreads();   // all warps done reading Q staging before tile0 overwrite

    // cp.async tile loader mapping
    const int fj = tid >> 2, fq = (tid & 3) * 8;
    const uint32_t dK = sb + (fj * 36 + fq) * 4;
    const uint32_t dV = sb + (4608 + fj * 36 + fq) * 4;

#define FCP(kt, buf) do { \
    cpa(dK + (buf) * FBUF * 4,               &g_kph[nh][(kt) * 64 + fj][fq]); \
    cpa(dK + (buf) * FBUF * 4 + 16,          &g_kph[nh][(kt) * 64 + fj][fq + 4]); \
    cpa(dK + ((buf) * FBUF + 2304) * 4,      &g_kpl[nh][(kt) * 64 + fj][fq]); \
    cpa(dK + ((buf) * FBUF + 2304) * 4 + 16, &g_kpl[nh][(kt) * 64 + fj][fq + 4]); \
    cpa(dV + (buf) * FBUF * 4,               &g_vh[nh][fj][(kt) * 32 + fq]); \
    cpa(dV + (buf) * FBUF * 4 + 16,          &g_vh[nh][fj][(kt) * 32 + fq + 4]); \
    cpa(dV + ((buf) * FBUF + 2304) * 4,      &g_vl[nh][fj][(kt) * 32 + fq]); \
    cpa(dV + ((buf) * FBUF + 2304) * 4 + 16, &g_vl[nh][fj][(kt) * 32 + fq + 4]); \
    CP_COMMIT(); } while (0)

    FCP(0, 0);

    float o[8][4] = {};
    float ls0 = 0.f, ls1 = 0.f;
    const uint32_t* mr0 = g_mb + (size_t)(n * K_ + qt * 128 + r0) * 64;
    const uint32_t* mr1 = mr0 + 8 * 64;

    const uint32_t brow = (lane & 7) + ((lane & 16) ? 8u : 0u);
    const uint32_t bbyt = (lane & 8) ? 16u : 0u;

#pragma unroll 2
    for (int kt = 0; kt < 32; kt++) {
        const int buf = kt & 1;
        // mask prefetch first: LDG latency hides under QK MMAs
        const uint2 w0 = *(const uint2*)(mr0 + kt * 2);
        const uint2 w1 = *(const uint2*)(mr1 + kt * 2);
        CP_WAIT0();
        __syncthreads();
        if (kt + 1 < 32) { FCP(kt + 1, buf ^ 1); } else { CP_COMMIT(); }

        // S = Q K^T (3-term)
        float s[8][4] = {};
#pragma unroll
        for (int sp = 0; sp < 4; sp++) {
#pragma unroll
            for (int g = 0; g < 4; g++) {
                const uint32_t base = (buf * FBUF + (g * 16 + brow) * 36 + sp * 8) * 4 + bbyt;
                uint32_t kh4[4], kl4[4];
                ldm4(kh4, sb + base);
                ldm4(kl4, sb + 2304 * 4 + base);
#pragma unroll
                for (int t = 0; t < 2; t++) {
                    mma_bf16(s[g * 2 + t], afh[sp], kh4 + 2 * t);
                    mma_bf16(s[g * 2 + t], afl[sp], kh4 + 2 * t);
                    mma_bf16(s[g * 2 + t], afh[sp], kl4 + 2 * t);
                }
            }
        }

        // mask + exp2 (no-max softmax)
#pragma unroll
        for (int nt = 0; nt < 8; nt++) {
            const int jb = nt * 8 + 2 * tig;
#pragma unroll
            for (int cc = 0; cc < 4; cc++) {
                const int j = jb + (cc & 1);
                const uint32_t word = (cc < 2) ? ((j < 32) ? w0.x : w0.y)
                                               : ((j < 32) ? w1.x : w1.y);
                s[nt][cc] = ((word >> (j & 31)) & 1u) ? 0.f : ex2f(s[nt][cc]);
            }
            ls0 += s[nt][0] + s[nt][1];
            ls1 += s[nt][2] + s[nt][3];
        }

        // O += P V (P frags in registers)
#pragma unroll
        for (int sp = 0; sp < 4; sp++) {
            uint32_t aph[4], apl[4];
            bsplit(s[2 * sp][0],     s[2 * sp][1],     aph[0], apl[0]);
            bsplit(s[2 * sp][2],     s[2 * sp][3],     aph[1], apl[1]);
            bsplit(s[2 * sp + 1][0], s[2 * sp + 1][1], aph[2], apl[2]);
            bsplit(s[2 * sp + 1][2], s[2 * sp + 1][3], aph[3], apl[3]);
#pragma unroll
            for (int g = 0; g < 4; g++) {
                const uint32_t base = (buf * FBUF + 4608 + (g * 16 + brow) * 36 + sp * 8) * 4 + bbyt;
                uint32_t vh4[4], vl4[4];
                ldm4(vh4, sb + base);
                ldm4(vl4, sb + 2304 * 4 + base);
#pragma unroll
                for (int t = 0; t < 2; t++) {
                    mma_bf16(o[g * 2 + t], aph, vh4 + 2 * t);
                    mma_bf16(o[g * 2 + t], apl, vh4 + 2 * t);
                    mma_bf16(o[g * 2 + t], aph, vl4 + 2 * t);
                }
            }
        }
    }

    // epilogue: row sums, normalize, write split outproj-A planes
    ls0 += __shfl_xor_sync(0xffffffffu, ls0, 1);
    ls0 += __shfl_xor_sync(0xffffffffu, ls0, 2);
    ls1 += __shfl_xor_sync(0xffffffffu, ls1, 1);
    ls1 += __shfl_xor_sync(0xffffffffu, ls1, 2);
    const float i0 = 1.0f / ls0, i1 = 1.0f / ls1;
    const int row = n * K_ + qt * 128 + r0;
#pragma unroll
    for (int dn = 0; dn < 8; dn++) {
        const int dp = h * 32 + dn * 4 + tig;
        uint32_t hh, ll;
        bsplit(o[dn][0] * i0, o[dn][1] * i0, hh, ll);
        g_yah[row][dp] = hh;  g_yal[row][dp] = ll;
        bsplit(o[dn][2] * i1, o[dn][3] * i1, hh, ll);
        g_yah[row + 8][dp] = hh;  g_yal[row + 8][dp] = ll;
    }
}

// ---------------- launch ----------------
extern "C" void kernel_launch(void* const* d_in, const int* in_sizes, int n_in,
                              void* d_out, int out_size)
{
    const float* query = (const float*)d_in[0];
    const float* key   = (const float*)d_in[1];
    const float* value = (const float*)d_in[2];
    const int*   mask  = (const int*)d_in[3];
    const float* Wq = (const float*)d_in[4];
    const float* bq = (const float*)d_in[5];
    const float* Wk = (const float*)d_in[6];
    const float* bk = (const float*)d_in[7];
    const float* Wv = (const float*)d_in[8];
    const float* bv = (const float*)d_in[9];
    const float* Wp = (const float*)d_in[10];
    const float* bp = (const float*)d_in[11];
    float* out = (float*)d_out;

    cudaFuncSetAttribute(gemm_mma, cudaFuncAttributeMaxDynamicSharedMemorySize, GEMM_SMEM);
    cudaFuncSetAttribute(flash_mma, cudaFuncAttributeMaxDynamicSharedMemorySize, FLASH_SMEM);

    mask_pack<<<(N_ * K_ * K_) / 256, 256>>>(mask);
    split_a<<<dim3(4096, 3), 256>>>(query, key, value);
    split_w<<<dim3(512, 4), 256>>>(Wq, Wk, Wv, Wp);
    gemm_mma<<<dim3(32, 8, 3), 256, GEMM_SMEM>>>(0, bq, bk, bv, bp, nullptr);
    repack_v<<<dim3(32, 32), 256>>>();
    flash_mma<<<dim3(16, 32), 256, FLASH_SMEM>>>();
    gemm_mma<<<dim3(32, 8, 1), 256, GEMM_SMEM>>>(1, bq, bk, bv, bp, out);
}